// round 4
// baseline (speedup 1.0000x reference)
#include <cuda_runtime.h>
#include <cuda_bf16.h>
#include <cstdint>

// Problem constants
constexpr int B_ = 256;   // batch
constexpr int T_ = 128;   // trees
constexpr int N_ = 256;   // nodes (= classes)
constexpr int E_ = 64;    // embedding
constexpr int H_ = 16;    // hidden
constexpr int K2_ = (T_ - 1) * H_;  // 2032

// Scratch (device globals; no runtime allocation)
__device__ __nv_bfloat16 g_be[T_ * B_ * E_];  // [j][b][e] bf16, 4 MB
__device__ __nv_bfloat16 g_zb[T_ * B_ * E_];  // [i][b][e] bf16, 4 MB

// ---------------------------------------------------------------------------
// Kernel 1: gather embeddings (shifted index) -> bf16 [j][b][e]
// 2 threads per row (half-row each) for 2x parallelism vs R3.
// ---------------------------------------------------------------------------
__global__ void gather_bf16_kernel(const int* __restrict__ x,
                                   const float* __restrict__ emb) {
    int j    = blockIdx.x;
    int b    = blockIdx.y * 64 + (threadIdx.x >> 1);
    int half = threadIdx.x & 1;
    int row  = x[b * T_ + j] + j * N_;
    const float4* src =
        reinterpret_cast<const float4*>(emb + (size_t)row * E_ + half * 32);
    __nv_bfloat162 v[16];
#pragma unroll
    for (int k = 0; k < 8; ++k) {
        float4 f = src[k];
        v[2 * k + 0] = __floats2bfloat162_rn(f.x, f.y);
        v[2 * k + 1] = __floats2bfloat162_rn(f.z, f.w);
    }
    uint4* dst = reinterpret_cast<uint4*>(
        g_be + ((size_t)j * B_ + b) * E_ + half * 32);
    const uint4* vp = reinterpret_cast<const uint4*>(v);
#pragma unroll
    for (int k = 0; k < 4; ++k) dst[k] = vp[k];
}

// ---------------------------------------------------------------------------
// mma.sync m16n8k16 bf16 (fp32 accum)
// ---------------------------------------------------------------------------
__device__ __forceinline__ void mma_bf16(float* c, const uint32_t* a,
                                         const uint32_t* b) {
    asm volatile(
        "mma.sync.aligned.m16n8k16.row.col.f32.bf16.bf16.f32 "
        "{%0,%1,%2,%3}, {%4,%5,%6,%7}, {%8,%9}, {%0,%1,%2,%3};"
        : "+f"(c[0]), "+f"(c[1]), "+f"(c[2]), "+f"(c[3])
        : "r"(a[0]), "r"(a[1]), "r"(a[2]), "r"(a[3]), "r"(b[0]), "r"(b[1]));
}

#define CP_ASYNC16(dst, src)                                         \
    asm volatile("cp.async.cg.shared.global [%0], [%1], 16;" ::      \
                 "r"(dst), "l"(src))
#define CP_COMMIT() asm volatile("cp.async.commit_group;" ::: "memory")
#define CP_WAIT1()  asm volatile("cp.async.wait_group 1;" ::: "memory")
#define CP_WAIT0()  asm volatile("cp.async.wait_group 0;" ::: "memory")

// Fused-kernel SMEM layout (bytes)
constexpr int BE_STRIDE = 144;              // 64 bf16 + 8 pad (conflict-free)
constexpr int BE_BUF    = 128 * BE_STRIDE;  // 18432 (128 batch rows)
constexpr int W1_STRIDE = 144;              // [h][e] bf16
constexpr int W1_BUF    = 16 * W1_STRIDE;   // 2304
constexpr int W2_STRIDE = 48;               // [e][h] bf16
constexpr int W2_BUF    = 64 * W2_STRIDE;   // 3072
constexpr int OFF_BE = 0;                            // 3 bufs
constexpr int OFF_W1 = OFF_BE + 3 * BE_BUF;          // 55296 (2buf x 2tree)
constexpr int OFF_W2 = OFF_W1 + 4 * W1_BUF;          // 64512 (2buf x 2tree)
constexpr int OFF_B1 = OFF_W2 + 4 * W2_BUF;          // 76800 (2 trees)
constexpr int OFF_B2 = OFF_B1 + 2 * T_ * H_ * 4;     // 93184 (2 trees)
constexpr int SMEM_TOTAL = OFF_B2 + 2 * E_ * 4;      // 93696

// ---------------------------------------------------------------------------
// Kernel 2: fused stages 2+3+4 on tensor cores, 2 trees per CTA.
// grid (2, 64): blockIdx.x = batch half h, blockIdx.y = g; trees {g, g+64}.
// 256 threads = 8 warps; warp w owns batch rows h*128 + [16w, 16w+16).
// Loop over ALL j in 0..127 (same order for every CTA -> L2 locality);
// GEMM2 skipped (uniformly) for the tree with j == i_t.
// BE: 3-stage cp.async ring; weights: register-staged LDG pipeline.
// ---------------------------------------------------------------------------
__global__ void __launch_bounds__(256, 1)
fused_mma_kernel(const float* __restrict__ lin1,   // [T,T,E,H]
                 const float* __restrict__ b1,     // [T,T,H]
                 const float* __restrict__ lin2,   // [T,(T-1)*H,E]
                 const float* __restrict__ b2) {   // [T,E]
    extern __shared__ char smem[];
    const int h    = blockIdx.x;
    const int g    = blockIdx.y;
    const int tid  = threadIdx.x;
    const int w    = tid >> 5;
    const int lane = tid & 31;
    const int q    = lane & 3;
    const int r4   = lane >> 2;

    float* sb1 = reinterpret_cast<float*>(smem + OFF_B1);   // [2][128*16]
    float* sb2 = reinterpret_cast<float*>(smem + OFF_B2);   // [2][64]
    const uint32_t smem_u32 = (uint32_t)__cvta_generic_to_shared(smem);

    // stage this CTA's 128 BE rows of tree-input j (no commit here)
    auto stage_be = [&](int buf, int j) {
        uint32_t dst0 = smem_u32 + OFF_BE + buf * BE_BUF;
        const char* src = reinterpret_cast<const char*>(
            g_be + ((size_t)j * B_ + h * 128) * E_);
#pragma unroll
        for (int u = 0; u < 4; ++u) {
            int c = tid + 256 * u;            // 1024 x 16B chunks
            int row = c >> 3, off = c & 7;
            CP_ASYNC16(dst0 + row * BE_STRIDE + off * 16, src + c * 16);
        }
    };

    struct WRegs { float4 v1[2], v2[2]; };
    auto ldg_w = [&](int j) {
        WRegs r;
#pragma unroll
        for (int t = 0; t < 2; ++t) {
            const int it = g + t * 64;
            r.v1[t] = reinterpret_cast<const float4*>(
                lin1 + (size_t)(it * T_ + j) * (E_ * H_))[tid];
            const int kk = (j > it) ? j - 1 : ((j < it) ? j : 0);
            r.v2[t] = reinterpret_cast<const float4*>(
                lin2 + ((size_t)it * K2_ + (size_t)kk * H_) * E_)[tid];
        }
        return r;
    };
    auto sts_w = [&](int buf, const WRegs& r) {
#pragma unroll
        for (int t = 0; t < 2; ++t) {
            __nv_bfloat16* w1 = reinterpret_cast<__nv_bfloat16*>(
                smem + OFF_W1 + (buf * 2 + t) * W1_BUF);
            {
                int idx = tid * 4;
                const float* f = reinterpret_cast<const float*>(&r.v1[t]);
#pragma unroll
                for (int s = 0; s < 4; ++s) {
                    int e = (idx + s) >> 4, hh = (idx + s) & 15;
                    w1[hh * (W1_STRIDE / 2) + e] = __float2bfloat16(f[s]);
                }
            }
            __nv_bfloat16* w2 = reinterpret_cast<__nv_bfloat16*>(
                smem + OFF_W2 + (buf * 2 + t) * W2_BUF);
            {
                int idx = tid * 4;
                const float* f = reinterpret_cast<const float*>(&r.v2[t]);
#pragma unroll
                for (int s = 0; s < 4; ++s) {
                    int k = (idx + s) >> 6, e = (idx + s) & 63;
                    w2[e * (W2_STRIDE / 2) + k] = __float2bfloat16(f[s]);
                }
            }
        }
    };

    // ---- prologue ----------------------------------------------------------
#pragma unroll
    for (int t = 0; t < 2; ++t) {
        const size_t base = (size_t)(g + t * 64) * T_ * H_;
#pragma unroll
        for (int u = 0; u < 8; ++u)
            sb1[t * 2048 + tid + 256 * u] = b1[base + tid + 256 * u];
    }
    if (tid < 128) {
        int t = tid >> 6, e = tid & 63;
        sb2[tid] = b2[(size_t)(g + t * 64) * E_ + e];
    }

    stage_be(0, 0); CP_COMMIT();
    WRegs w0 = ldg_w(0);
    sts_w(0, w0);
    stage_be(1, 1); CP_COMMIT();
    WRegs wr = ldg_w(1);          // invariant: wr = W(jj+1)

    float zacc[2][8][4];
#pragma unroll
    for (int t = 0; t < 2; ++t)
#pragma unroll
        for (int nt = 0; nt < 8; ++nt)
#pragma unroll
            for (int s = 0; s < 4; ++s) zacc[t][nt][s] = 0.f;

    // ---- main loop over ALL j --------------------------------------------
    for (int j = 0; j < T_; ++j) {
        CP_WAIT1();               // BE(j) complete
        __syncthreads();

        if (j + 1 < T_) sts_w((j + 1) & 1, wr);
        if (j + 2 < T_) {
            wr = ldg_w(j + 2);
            stage_be((j + 2) % 3, j + 2);
        }
        CP_COMMIT();

        const char* BEb = smem + OFF_BE + (j % 3) * BE_BUF;

        // A-fragments: one m16k64 strip per warp, shared by both trees
        uint32_t a[4][4];
#pragma unroll
        for (int kt = 0; kt < 4; ++kt) {
            const char* pa = BEb + (w * 16 + r4) * BE_STRIDE + kt * 32 + q * 4;
            a[kt][0] = *reinterpret_cast<const uint32_t*>(pa);
            a[kt][1] = *reinterpret_cast<const uint32_t*>(pa + 8 * BE_STRIDE);
            a[kt][2] = *reinterpret_cast<const uint32_t*>(pa + 16);
            a[kt][3] = *reinterpret_cast<const uint32_t*>(pa + 8 * BE_STRIDE + 16);
        }

#pragma unroll
        for (int t = 0; t < 2; ++t) {
            const int it = g + t * 64;
            const char* W1b = smem + OFF_W1 + ((j & 1) * 2 + t) * W1_BUF;

            // GEMM1: tmp[16,16] = BE[16,64] @ W1[64,16] (+bias)
            float c1[2][4];
#pragma unroll
            for (int nt = 0; nt < 2; ++nt) {
                float bv0 = sb1[t * 2048 + j * H_ + nt * 8 + 2 * q];
                float bv1 = sb1[t * 2048 + j * H_ + nt * 8 + 2 * q + 1];
                c1[nt][0] = bv0; c1[nt][1] = bv1;
                c1[nt][2] = bv0; c1[nt][3] = bv1;
            }
#pragma unroll
            for (int kt = 0; kt < 4; ++kt) {
                uint32_t bb[2][2];
#pragma unroll
                for (int nt = 0; nt < 2; ++nt) {
                    const char* pw =
                        W1b + (nt * 8 + r4) * W1_STRIDE + kt * 32 + q * 4;
                    bb[nt][0] = *reinterpret_cast<const uint32_t*>(pw);
                    bb[nt][1] = *reinterpret_cast<const uint32_t*>(pw + 16);
                }
#pragma unroll
                for (int nt = 0; nt < 2; ++nt)
                    mma_bf16(c1[nt], a[kt], bb[nt]);
            }

            if (j != it) {        // CTA-uniform: skip GEMM2 when j == tree
                // relu + cvt -> GEMM2 A-fragment (registers only)
#pragma unroll
                for (int nt = 0; nt < 2; ++nt)
#pragma unroll
                    for (int s = 0; s < 4; ++s)
                        c1[nt][s] = fmaxf(c1[nt][s], 0.f);
                uint32_t a2[4];
                __nv_bfloat162 p0 = __floats2bfloat162_rn(c1[0][0], c1[0][1]);
                __nv_bfloat162 p1 = __floats2bfloat162_rn(c1[0][2], c1[0][3]);
                __nv_bfloat162 p2 = __floats2bfloat162_rn(c1[1][0], c1[1][1]);
                __nv_bfloat162 p3 = __floats2bfloat162_rn(c1[1][2], c1[1][3]);
                a2[0] = *reinterpret_cast<uint32_t*>(&p0);
                a2[1] = *reinterpret_cast<uint32_t*>(&p1);
                a2[2] = *reinterpret_cast<uint32_t*>(&p2);
                a2[3] = *reinterpret_cast<uint32_t*>(&p3);

                const char* W2b =
                    smem + OFF_W2 + ((j & 1) * 2 + t) * W2_BUF;
#pragma unroll
                for (int nt = 0; nt < 8; ++nt) {
                    const char* pw = W2b + (nt * 8 + r4) * W2_STRIDE + q * 4;
                    uint32_t b2f[2];
                    b2f[0] = *reinterpret_cast<const uint32_t*>(pw);
                    b2f[1] = *reinterpret_cast<const uint32_t*>(pw + 16);
                    mma_bf16(zacc[t][nt], a2, b2f);
                }
            }
        }
    }

    // ---- epilogue: (z + bias2) -> g_zb[i_t][b][e] bf16 ---------------------
#pragma unroll
    for (int t = 0; t < 2; ++t) {
        const int it = g + t * 64;
        const int row0 = h * 128 + w * 16 + r4;
#pragma unroll
        for (int nt = 0; nt < 8; ++nt) {
            int e = nt * 8 + 2 * q;
            float bx = sb2[t * 64 + e], by = sb2[t * 64 + e + 1];
            __nv_bfloat162 v0 =
                __floats2bfloat162_rn(zacc[t][nt][0] + bx, zacc[t][nt][1] + by);
            __nv_bfloat162 v1 =
                __floats2bfloat162_rn(zacc[t][nt][2] + bx, zacc[t][nt][3] + by);
            *reinterpret_cast<__nv_bfloat162*>(
                g_zb + ((size_t)it * B_ + row0) * E_ + e) = v0;
            *reinterpret_cast<__nv_bfloat162*>(
                g_zb + ((size_t)it * B_ + row0 + 8) * E_ + e) = v1;
        }
    }
}

// ---------------------------------------------------------------------------
// Kernel 3: logits + CE head on tensor cores (as R3).
// ---------------------------------------------------------------------------
constexpr int HS_ZS  = 0;                       // 256 rows x 144B
constexpr int HS_W3  = 256 * 144;               // [n][e] bf16, 144B rows
constexpr int HSMEM_TOTAL = HS_W3 + 256 * 144;  // 73728

__global__ void __launch_bounds__(256, 1)
head_mma_kernel(const int* __restrict__ x,
                const float* __restrict__ w3g,   // [T,E,N]
                float* __restrict__ out) {       // [B,T]
    extern __shared__ char smem[];
    const int t    = blockIdx.x;
    const int tid  = threadIdx.x;
    const int w    = tid >> 5;
    const int lane = tid & 31;
    const int q    = lane & 3;
    const int r4   = lane >> 2;
    const uint32_t smem_u32 = (uint32_t)__cvta_generic_to_shared(smem);

    // stage z[t] tile (256x64 bf16) via cp.async
    {
        uint32_t dst0 = smem_u32 + HS_ZS;
        const char* src =
            reinterpret_cast<const char*>(g_zb + (size_t)t * B_ * E_);
#pragma unroll
        for (int u = 0; u < 8; ++u) {
            int c = tid + 256 * u;
            int row = c >> 3, off = c & 7;
            CP_ASYNC16(dst0 + row * BE_STRIDE + off * 16, src + c * 16);
        }
        CP_COMMIT();
    }

    // transpose W3[t] fp32 [e][n] -> smem bf16 [n][e]
    {
        const float4* w3p = reinterpret_cast<const float4*>(
            w3g + (size_t)t * E_ * N_);
        __nv_bfloat16* W3S = reinterpret_cast<__nv_bfloat16*>(smem + HS_W3);
#pragma unroll
        for (int it = 0; it < 16; ++it) {
            int idx = it * 256 + tid;
            float4 f = w3p[idx];
            int e = idx >> 6, n0 = (idx & 63) * 4;
            W3S[(n0 + 0) * 72 + e] = __float2bfloat16(f.x);
            W3S[(n0 + 1) * 72 + e] = __float2bfloat16(f.y);
            W3S[(n0 + 2) * 72 + e] = __float2bfloat16(f.z);
            W3S[(n0 + 3) * 72 + e] = __float2bfloat16(f.w);
        }
    }
    CP_WAIT0();
    __syncthreads();

    uint32_t a[4][2][4];
#pragma unroll
    for (int kt = 0; kt < 4; ++kt)
#pragma unroll
        for (int mt = 0; mt < 2; ++mt) {
            int row = w * 32 + mt * 16 + r4;
            const char* pa = smem + HS_ZS + row * BE_STRIDE + kt * 32 + q * 4;
            a[kt][mt][0] = *reinterpret_cast<const uint32_t*>(pa);
            a[kt][mt][1] = *reinterpret_cast<const uint32_t*>(pa + 8 * BE_STRIDE);
            a[kt][mt][2] = *reinterpret_cast<const uint32_t*>(pa + 16);
            a[kt][mt][3] = *reinterpret_cast<const uint32_t*>(pa + 8 * BE_STRIDE + 16);
        }

    int xv[2][2];
#pragma unroll
    for (int mt = 0; mt < 2; ++mt)
#pragma unroll
        for (int hh = 0; hh < 2; ++hh)
            xv[mt][hh] = x[(size_t)(w * 32 + mt * 16 + r4 + 8 * hh) * T_ + t];

    float sum[2][2] = {{0.f, 0.f}, {0.f, 0.f}};
    float picked[2][2] = {{0.f, 0.f}, {0.f, 0.f}};

#pragma unroll
    for (int n0 = 0; n0 < 4; ++n0) {
        float c[2][8][4];
#pragma unroll
        for (int mt = 0; mt < 2; ++mt)
#pragma unroll
            for (int nt = 0; nt < 8; ++nt)
#pragma unroll
                for (int s = 0; s < 4; ++s) c[mt][nt][s] = 0.f;

#pragma unroll
        for (int kt = 0; kt < 4; ++kt) {
            uint32_t bb[8][2];
#pragma unroll
            for (int nt = 0; nt < 8; ++nt) {
                const char* pw = smem + HS_W3 +
                    (n0 * 64 + nt * 8 + r4) * 144 + kt * 32 + q * 4;
                bb[nt][0] = *reinterpret_cast<const uint32_t*>(pw);
                bb[nt][1] = *reinterpret_cast<const uint32_t*>(pw + 16);
            }
#pragma unroll
            for (int nt = 0; nt < 8; ++nt)
#pragma unroll
                for (int mt = 0; mt < 2; ++mt)
                    mma_bf16(c[mt][nt], a[kt][mt], bb[nt]);
        }

#pragma unroll
        for (int mt = 0; mt < 2; ++mt)
#pragma unroll
            for (int nt = 0; nt < 8; ++nt)
#pragma unroll
                for (int s = 0; s < 4; ++s) {
                    int n = n0 * 64 + nt * 8 + 2 * q + (s & 1);
                    int hh = s >> 1;
                    float v = c[mt][nt][s];
                    sum[mt][hh] += __expf(v);
                    if (n == xv[mt][hh]) picked[mt][hh] = v;
                }
    }

#pragma unroll
    for (int mt = 0; mt < 2; ++mt)
#pragma unroll
        for (int hh = 0; hh < 2; ++hh) {
            float s = sum[mt][hh], p = picked[mt][hh];
            s += __shfl_xor_sync(0xffffffffu, s, 1);
            s += __shfl_xor_sync(0xffffffffu, s, 2);
            p += __shfl_xor_sync(0xffffffffu, p, 1);
            p += __shfl_xor_sync(0xffffffffu, p, 2);
            if (q == 0) {
                int row = w * 32 + mt * 16 + r4 + 8 * hh;
                out[(size_t)row * T_ + t] = __logf(s) - p;
            }
        }
}

// ---------------------------------------------------------------------------
extern "C" void kernel_launch(void* const* d_in, const int* in_sizes, int n_in,
                              void* d_out, int out_size) {
    const int*   x    = (const int*)  d_in[0];  // [B,T]
    const float* emb  = (const float*)d_in[1];  // [N*T,E]
    const float* lin1 = (const float*)d_in[2];  // [T,T,E,H]
    const float* b1   = (const float*)d_in[3];  // [T,T,H]
    const float* lin2 = (const float*)d_in[4];  // [T,(T-1)*H,E]
    const float* b2   = (const float*)d_in[5];  // [T,E]
    const float* w3   = (const float*)d_in[6];  // [T,E,N]
    float* out = (float*)d_out;                 // [B,T]

    cudaFuncSetAttribute(fused_mma_kernel,
                         cudaFuncAttributeMaxDynamicSharedMemorySize,
                         SMEM_TOTAL);
    cudaFuncSetAttribute(head_mma_kernel,
                         cudaFuncAttributeMaxDynamicSharedMemorySize,
                         HSMEM_TOTAL);

    gather_bf16_kernel<<<dim3(T_, B_ / 64), 128>>>(x, emb);
    fused_mma_kernel<<<dim3(2, 64), 256, SMEM_TOTAL>>>(lin1, b1, lin2, b2);
    head_mma_kernel<<<T_, 256, HSMEM_TOTAL>>>(x, w3, out);
}

// round 6
// speedup vs baseline: 1.0517x; 1.0517x over previous
#include <cuda_runtime.h>
#include <cuda_bf16.h>
#include <cstdint>

// Problem constants
constexpr int B_ = 256;   // batch
constexpr int T_ = 128;   // trees
constexpr int N_ = 256;   // nodes (= classes)
constexpr int E_ = 64;    // embedding
constexpr int H_ = 16;    // hidden
constexpr int K2_ = (T_ - 1) * H_;  // 2032

// Scratch (device global; no runtime allocation)
__device__ __nv_bfloat16 g_be[T_ * B_ * E_];  // [j][b][e] bf16, 4 MB

// ---------------------------------------------------------------------------
// Kernel 1: gather embeddings (shifted index) -> bf16 [j][b][e]
// ---------------------------------------------------------------------------
__global__ void gather_bf16_kernel(const int* __restrict__ x,
                                   const float* __restrict__ emb) {
    int j    = blockIdx.x;
    int b    = blockIdx.y * 64 + (threadIdx.x >> 1);
    int half = threadIdx.x & 1;
    int row  = x[b * T_ + j] + j * N_;
    const float4* src =
        reinterpret_cast<const float4*>(emb + (size_t)row * E_ + half * 32);
    __nv_bfloat162 v[16];
#pragma unroll
    for (int k = 0; k < 8; ++k) {
        float4 f = src[k];
        v[2 * k + 0] = __floats2bfloat162_rn(f.x, f.y);
        v[2 * k + 1] = __floats2bfloat162_rn(f.z, f.w);
    }
    uint4* dst = reinterpret_cast<uint4*>(
        g_be + ((size_t)j * B_ + b) * E_ + half * 32);
    const uint4* vp = reinterpret_cast<const uint4*>(v);
#pragma unroll
    for (int k = 0; k < 4; ++k) dst[k] = vp[k];
}

// ---------------------------------------------------------------------------
// mma.sync m16n8k16 bf16 (fp32 accum)
// ---------------------------------------------------------------------------
__device__ __forceinline__ void mma_bf16(float* c, const uint32_t* a,
                                         const uint32_t* b) {
    asm volatile(
        "mma.sync.aligned.m16n8k16.row.col.f32.bf16.bf16.f32 "
        "{%0,%1,%2,%3}, {%4,%5,%6,%7}, {%8,%9}, {%0,%1,%2,%3};"
        : "+f"(c[0]), "+f"(c[1]), "+f"(c[2]), "+f"(c[3])
        : "r"(a[0]), "r"(a[1]), "r"(a[2]), "r"(a[3]), "r"(b[0]), "r"(b[1]));
}

#define CP_ASYNC16(dst, src)                                         \
    asm volatile("cp.async.cg.shared.global [%0], [%1], 16;" ::      \
                 "r"(dst), "l"(src))
#define CP_COMMIT() asm volatile("cp.async.commit_group;" ::: "memory")
#define CP_WAIT1()  asm volatile("cp.async.wait_group 1;" ::: "memory")
#define CP_WAIT0()  asm volatile("cp.async.wait_group 0;" ::: "memory")

// Fused-kernel SMEM layout (bytes)
constexpr int BE_STRIDE = 144;              // 64 bf16 + 8 pad (conflict-free)
constexpr int BE_BUF    = 256 * BE_STRIDE;  // 36864 (256 batch rows)
constexpr int W1_STRIDE = 144;              // [h][e] bf16
constexpr int W1_BUF    = 16 * W1_STRIDE;   // 2304
constexpr int W2_STRIDE = 48;               // [e][h] bf16
constexpr int W2_BUF    = 64 * W2_STRIDE;   // 3072
constexpr int OFF_BE = 0;                            // 3 bufs (110592)
constexpr int OFF_W1 = OFF_BE + 3 * BE_BUF;          // 110592
constexpr int OFF_W2 = OFF_W1 + 2 * W1_BUF;          // 115200
constexpr int OFF_B1 = OFF_W2 + 2 * W2_BUF;          // 121344
constexpr int OFF_B2 = OFF_B1 + T_ * H_ * 4;         // 129536
constexpr int SMEM_TOTAL = OFF_B2 + E_ * 4;          // 129792
// W3 bf16 [n][e] staging overlays the dead BE ring in the epilogue
constexpr int OFF_W3S = 0;                  // 256 rows x 144B = 36864

// ---------------------------------------------------------------------------
// Kernel 2: fully fused stages 2..7 (GEMM1+relu+GEMM2+bias | logits+CE).
// CTA = tree i (grid 128). 512 threads = 16 warps; warp w owns batch rows
// [16w, 16w+16). z[16,64] fp32 accumulators in registers; z NEVER hits memory.
// BE: 3-stage cp.async ring; weights: register-staged LDG pipeline (dist 2).
// ---------------------------------------------------------------------------
__global__ void __launch_bounds__(512, 1)
fused_all_kernel(const float* __restrict__ lin1,   // [T,T,E,H]
                 const float* __restrict__ b1,     // [T,T,H]
                 const float* __restrict__ lin2,   // [T,(T-1)*H,E]
                 const float* __restrict__ b2,     // [T,E]
                 const float* __restrict__ w3g,    // [T,E,N]
                 const int*   __restrict__ x,      // [B,T]
                 float* __restrict__ out) {        // [B,T]
    extern __shared__ char smem[];
    const int i    = blockIdx.x;
    const int tid  = threadIdx.x;
    const int w    = tid >> 5;
    const int lane = tid & 31;
    const int q    = lane & 3;
    const int r4   = lane >> 2;

    float* sb1 = reinterpret_cast<float*>(smem + OFF_B1);
    float* sb2 = reinterpret_cast<float*>(smem + OFF_B2);
    const uint32_t smem_u32 = (uint32_t)__cvta_generic_to_shared(smem);

    auto jof = [&](int jj) { return jj + (jj >= i); };

    // stage BE[j] (256 rows) into ring buffer buf (no commit here)
    auto stage_be = [&](int buf, int j) {
        uint32_t dst0 = smem_u32 + OFF_BE + buf * BE_BUF;
        const char* src =
            reinterpret_cast<const char*>(g_be + (size_t)j * B_ * E_);
#pragma unroll
        for (int u = 0; u < 4; ++u) {
            int c = tid + 512 * u;             // 2048 x 16B chunks
            int row = c >> 3, off = c & 7;
            CP_ASYNC16(dst0 + row * BE_STRIDE + off * 16, src + c * 16);
        }
    };

    struct WRegs { float2 v1, v2; };
    auto ldg_w = [&](int j) {
        WRegs r;
        r.v1 = reinterpret_cast<const float2*>(
            lin1 + (size_t)(i * T_ + j) * (E_ * H_))[tid];
        int kk = (j < i) ? j : j - 1;
        r.v2 = reinterpret_cast<const float2*>(
            lin2 + ((size_t)i * K2_ + (size_t)kk * H_) * E_)[tid];
        return r;
    };
    auto sts_w = [&](int buf, const WRegs& r) {
        __nv_bfloat16* w1 =
            reinterpret_cast<__nv_bfloat16*>(smem + OFF_W1 + buf * W1_BUF);
        {
            int idx = tid * 2;
            const float* f = reinterpret_cast<const float*>(&r.v1);
#pragma unroll
            for (int s = 0; s < 2; ++s) {
                int e = (idx + s) >> 4, hh = (idx + s) & 15;
                w1[hh * (W1_STRIDE / 2) + e] = __float2bfloat16(f[s]);
            }
        }
        __nv_bfloat16* w2 =
            reinterpret_cast<__nv_bfloat16*>(smem + OFF_W2 + buf * W2_BUF);
        {
            int idx = tid * 2;
            const float* f = reinterpret_cast<const float*>(&r.v2);
#pragma unroll
            for (int s = 0; s < 2; ++s) {
                int k = (idx + s) >> 6, e = (idx + s) & 63;
                w2[e * (W2_STRIDE / 2) + k] = __float2bfloat16(f[s]);
            }
        }
    };

    // ---- prologue ----------------------------------------------------------
#pragma unroll
    for (int u = 0; u < 4; ++u)
        sb1[tid + 512 * u] = b1[(size_t)i * T_ * H_ + tid + 512 * u];
    if (tid < E_) sb2[tid] = b2[(size_t)i * E_ + tid];

    stage_be(0, jof(0)); CP_COMMIT();
    WRegs w0 = ldg_w(jof(0));
    sts_w(0, w0);
    stage_be(1, jof(1)); CP_COMMIT();
    WRegs wr = ldg_w(jof(1));              // invariant: wr = W(jj+1)

    float zacc[8][4];
#pragma unroll
    for (int nt = 0; nt < 8; ++nt)
#pragma unroll
        for (int s = 0; s < 4; ++s) zacc[nt][s] = 0.f;

    // ---- main loop over jj (j != i) ---------------------------------------
    for (int jj = 0; jj < T_ - 1; ++jj) {
        const int j = jof(jj);

        CP_WAIT1();              // BE(jj) complete
        __syncthreads();

        if (jj + 1 < T_ - 1) sts_w((jj + 1) & 1, wr);
        if (jj + 2 < T_ - 1) {
            wr = ldg_w(jof(jj + 2));
            stage_be((jj + 2) % 3, jof(jj + 2));
        }
        CP_COMMIT();             // one group per iteration (maybe empty)

        const char* BEb = smem + OFF_BE + (jj % 3) * BE_BUF;
        const char* W1b = smem + OFF_W1 + (jj & 1) * W1_BUF;
        const char* W2b = smem + OFF_W2 + (jj & 1) * W2_BUF;

        // A-fragments: m16k64 strip for this warp's 16 rows
        uint32_t a[4][4];
#pragma unroll
        for (int kt = 0; kt < 4; ++kt) {
            const char* pa = BEb + (w * 16 + r4) * BE_STRIDE + kt * 32 + q * 4;
            a[kt][0] = *reinterpret_cast<const uint32_t*>(pa);
            a[kt][1] = *reinterpret_cast<const uint32_t*>(pa + 8 * BE_STRIDE);
            a[kt][2] = *reinterpret_cast<const uint32_t*>(pa + 16);
            a[kt][3] = *reinterpret_cast<const uint32_t*>(pa + 8 * BE_STRIDE + 16);
        }

        // GEMM1: tmp[16,16] = BE[16,64] @ W1[64,16] (+bias1)
        float c1[2][4];
#pragma unroll
        for (int nt = 0; nt < 2; ++nt) {
            float bv0 = sb1[j * H_ + nt * 8 + 2 * q];
            float bv1 = sb1[j * H_ + nt * 8 + 2 * q + 1];
            c1[nt][0] = bv0; c1[nt][1] = bv1;
            c1[nt][2] = bv0; c1[nt][3] = bv1;
        }
#pragma unroll
        for (int kt = 0; kt < 4; ++kt) {
            uint32_t bb[2][2];
#pragma unroll
            for (int nt = 0; nt < 2; ++nt) {
                const char* pw = W1b + (nt * 8 + r4) * W1_STRIDE + kt * 32 + q * 4;
                bb[nt][0] = *reinterpret_cast<const uint32_t*>(pw);
                bb[nt][1] = *reinterpret_cast<const uint32_t*>(pw + 16);
            }
#pragma unroll
            for (int nt = 0; nt < 2; ++nt)
                mma_bf16(c1[nt], a[kt], bb[nt]);
        }

        // relu + cvt C-frags -> GEMM2 A-frag (registers only)
#pragma unroll
        for (int nt = 0; nt < 2; ++nt)
#pragma unroll
            for (int s = 0; s < 4; ++s) c1[nt][s] = fmaxf(c1[nt][s], 0.f);
        uint32_t a2[4];
        {
            __nv_bfloat162 p0 = __floats2bfloat162_rn(c1[0][0], c1[0][1]);
            __nv_bfloat162 p1 = __floats2bfloat162_rn(c1[0][2], c1[0][3]);
            __nv_bfloat162 p2 = __floats2bfloat162_rn(c1[1][0], c1[1][1]);
            __nv_bfloat162 p3 = __floats2bfloat162_rn(c1[1][2], c1[1][3]);
            a2[0] = *reinterpret_cast<uint32_t*>(&p0);
            a2[1] = *reinterpret_cast<uint32_t*>(&p1);
            a2[2] = *reinterpret_cast<uint32_t*>(&p2);
            a2[3] = *reinterpret_cast<uint32_t*>(&p3);
        }

        // GEMM2: z[16,64] += tmp[16,16] @ W2[16,64]
#pragma unroll
        for (int nt = 0; nt < 8; ++nt) {
            const char* pw = W2b + (nt * 8 + r4) * W2_STRIDE + q * 4;
            uint32_t b2f[2];
            b2f[0] = *reinterpret_cast<const uint32_t*>(pw);
            b2f[1] = *reinterpret_cast<const uint32_t*>(pw + 16);
            mma_bf16(zacc[nt], a2, b2f);
        }
    }

    // ======================= fused CE head ==================================
    CP_WAIT0();
    __syncthreads();             // BE ring dead; reuse as W3 staging

    // W3[i] fp32 [e][n] -> smem bf16 [n][e] (rows 144B)
    {
        const float4* w3p =
            reinterpret_cast<const float4*>(w3g + (size_t)i * E_ * N_);
        __nv_bfloat16* W3S = reinterpret_cast<__nv_bfloat16*>(smem + OFF_W3S);
#pragma unroll
        for (int it = 0; it < 8; ++it) {
            int idx = it * 512 + tid;          // 4096 float4 total
            float4 f = w3p[idx];
            int e = idx >> 6, n0 = (idx & 63) * 4;
            W3S[(n0 + 0) * 72 + e] = __float2bfloat16(f.x);
            W3S[(n0 + 1) * 72 + e] = __float2bfloat16(f.y);
            W3S[(n0 + 2) * 72 + e] = __float2bfloat16(f.z);
            W3S[(n0 + 3) * 72 + e] = __float2bfloat16(f.w);
        }
    }

    // z + bias2 -> bf16 A-fragments (e-chunk kt <- zacc nt pair {2kt,2kt+1})
    uint32_t az[4][4];
#pragma unroll
    for (int kt = 0; kt < 4; ++kt) {
        float v[2][4];
#pragma unroll
        for (int p = 0; p < 2; ++p) {
            int nt = 2 * kt + p;
            float bx = sb2[nt * 8 + 2 * q], by = sb2[nt * 8 + 2 * q + 1];
            v[p][0] = zacc[nt][0] + bx; v[p][1] = zacc[nt][1] + by;
            v[p][2] = zacc[nt][2] + bx; v[p][3] = zacc[nt][3] + by;
        }
        __nv_bfloat162 p0 = __floats2bfloat162_rn(v[0][0], v[0][1]);
        __nv_bfloat162 p1 = __floats2bfloat162_rn(v[0][2], v[0][3]);
        __nv_bfloat162 p2 = __floats2bfloat162_rn(v[1][0], v[1][1]);
        __nv_bfloat162 p3 = __floats2bfloat162_rn(v[1][2], v[1][3]);
        az[kt][0] = *reinterpret_cast<uint32_t*>(&p0);
        az[kt][1] = *reinterpret_cast<uint32_t*>(&p1);
        az[kt][2] = *reinterpret_cast<uint32_t*>(&p2);
        az[kt][3] = *reinterpret_cast<uint32_t*>(&p3);
    }

    int xv[2];
    xv[0] = x[(size_t)(w * 16 + r4) * T_ + i];
    xv[1] = x[(size_t)(w * 16 + r4 + 8) * T_ + i];

    __syncthreads();             // W3S ready

    float sum[2] = {0.f, 0.f};
    float picked[2] = {0.f, 0.f};

#pragma unroll
    for (int n0 = 0; n0 < 4; ++n0) {           // 64 classes per chunk
        float c[8][4];
#pragma unroll
        for (int nt = 0; nt < 8; ++nt)
#pragma unroll
            for (int s = 0; s < 4; ++s) c[nt][s] = 0.f;
#pragma unroll
        for (int kt = 0; kt < 4; ++kt) {
            uint32_t bb[8][2];
#pragma unroll
            for (int nt = 0; nt < 8; ++nt) {
                const char* pw = smem + OFF_W3S +
                    (n0 * 64 + nt * 8 + r4) * 144 + kt * 32 + q * 4;
                bb[nt][0] = *reinterpret_cast<const uint32_t*>(pw);
                bb[nt][1] = *reinterpret_cast<const uint32_t*>(pw + 16);
            }
#pragma unroll
            for (int nt = 0; nt < 8; ++nt)
                mma_bf16(c[nt], az[kt], bb[nt]);
        }
#pragma unroll
        for (int nt = 0; nt < 8; ++nt)
#pragma unroll
            for (int s = 0; s < 4; ++s) {
                int n = n0 * 64 + nt * 8 + 2 * q + (s & 1);
                int hh = s >> 1;
                float v = c[nt][s];
                sum[hh] += __expf(v);
                if (n == xv[hh]) picked[hh] = v;
            }
    }

    // reduce over the 4 q-lanes (consecutive lanes r4*4+q)
#pragma unroll
    for (int hh = 0; hh < 2; ++hh) {
        float s = sum[hh], p = picked[hh];
        s += __shfl_xor_sync(0xffffffffu, s, 1);
        s += __shfl_xor_sync(0xffffffffu, s, 2);
        p += __shfl_xor_sync(0xffffffffu, p, 1);
        p += __shfl_xor_sync(0xffffffffu, p, 2);
        if (q == 0) {
            int row = w * 16 + r4 + 8 * hh;
            out[(size_t)row * T_ + i] = __logf(s) - p;
        }
    }
}

// ---------------------------------------------------------------------------
extern "C" void kernel_launch(void* const* d_in, const int* in_sizes, int n_in,
                              void* d_out, int out_size) {
    const int*   x    = (const int*)  d_in[0];  // [B,T]
    const float* emb  = (const float*)d_in[1];  // [N*T,E]
    const float* lin1 = (const float*)d_in[2];  // [T,T,E,H]
    const float* b1   = (const float*)d_in[3];  // [T,T,H]
    const float* lin2 = (const float*)d_in[4];  // [T,(T-1)*H,E]
    const float* b2   = (const float*)d_in[5];  // [T,E]
    const float* w3   = (const float*)d_in[6];  // [T,E,N]
    float* out = (float*)d_out;                 // [B,T]

    cudaFuncSetAttribute(fused_all_kernel,
                         cudaFuncAttributeMaxDynamicSharedMemorySize,
                         SMEM_TOTAL);

    gather_bf16_kernel<<<dim3(T_, B_ / 64), 128>>>(x, emb);
    fused_all_kernel<<<T_, 512, SMEM_TOTAL>>>(lin1, b1, lin2, b2, w3, x, out);
}

// round 7
// speedup vs baseline: 1.1631x; 1.1060x over previous
#include <cuda_runtime.h>
#include <cuda_bf16.h>
#include <cstdint>

// Problem constants
constexpr int B_ = 256;   // batch
constexpr int T_ = 128;   // trees
constexpr int N_ = 256;   // nodes (= classes)
constexpr int E_ = 64;    // embedding
constexpr int H_ = 16;    // hidden
constexpr int K2_ = (T_ - 1) * H_;  // 2032

// Scratch (device global; no runtime allocation)
__device__ __nv_bfloat16 g_be[T_ * B_ * E_];  // [j][b][e] bf16, 4 MB

// ---------------------------------------------------------------------------
// Kernel 1: gather embeddings (shifted index) -> bf16 [j][b][e]
// ---------------------------------------------------------------------------
__global__ void gather_bf16_kernel(const int* __restrict__ x,
                                   const float* __restrict__ emb) {
    int j    = blockIdx.x;
    int b    = blockIdx.y * 64 + (threadIdx.x >> 1);
    int half = threadIdx.x & 1;
    int row  = x[b * T_ + j] + j * N_;
    const float4* src =
        reinterpret_cast<const float4*>(emb + (size_t)row * E_ + half * 32);
    __nv_bfloat162 v[16];
#pragma unroll
    for (int k = 0; k < 8; ++k) {
        float4 f = src[k];
        v[2 * k + 0] = __floats2bfloat162_rn(f.x, f.y);
        v[2 * k + 1] = __floats2bfloat162_rn(f.z, f.w);
    }
    uint4* dst = reinterpret_cast<uint4*>(
        g_be + ((size_t)j * B_ + b) * E_ + half * 32);
    const uint4* vp = reinterpret_cast<const uint4*>(v);
#pragma unroll
    for (int k = 0; k < 4; ++k) dst[k] = vp[k];
}

// ---------------------------------------------------------------------------
// mma.sync m16n8k16 bf16 (fp32 accum) + ldmatrix helpers
// ---------------------------------------------------------------------------
__device__ __forceinline__ void mma_bf16(float* c, const uint32_t* a,
                                         uint32_t b0, uint32_t b1) {
    asm volatile(
        "mma.sync.aligned.m16n8k16.row.col.f32.bf16.bf16.f32 "
        "{%0,%1,%2,%3}, {%4,%5,%6,%7}, {%8,%9}, {%0,%1,%2,%3};"
        : "+f"(c[0]), "+f"(c[1]), "+f"(c[2]), "+f"(c[3])
        : "r"(a[0]), "r"(a[1]), "r"(a[2]), "r"(a[3]), "r"(b0), "r"(b1));
}

#define LDSM_X4(r0, r1, r2, r3, addr)                                     \
    asm volatile("ldmatrix.sync.aligned.m8n8.x4.shared.b16 "              \
                 "{%0,%1,%2,%3}, [%4];"                                   \
                 : "=r"(r0), "=r"(r1), "=r"(r2), "=r"(r3) : "r"(addr))

#define CP_ASYNC16(dst, src)                                         \
    asm volatile("cp.async.cg.shared.global [%0], [%1], 16;" ::      \
                 "r"(dst), "l"(src))
#define CP_COMMIT() asm volatile("cp.async.commit_group;" ::: "memory")
#define CP_WAIT1()  asm volatile("cp.async.wait_group 1;" ::: "memory")
#define CP_WAIT0()  asm volatile("cp.async.wait_group 0;" ::: "memory")

// Fused-kernel SMEM layout (bytes)
constexpr int BE_STRIDE = 144;              // 64 bf16 + 8 pad (conflict-free)
constexpr int BE_BUF    = 256 * BE_STRIDE;  // 36864 (256 batch rows)
constexpr int W1_STRIDE = 144;              // [h][e] bf16
constexpr int W1_BUF    = 16 * W1_STRIDE;   // 2304
constexpr int W2_STRIDE = 48;               // [e][h] bf16
constexpr int W2_BUF    = 64 * W2_STRIDE;   // 3072
constexpr int OFF_BE = 0;                            // 3 bufs
constexpr int OFF_W1 = OFF_BE + 3 * BE_BUF;          // 110592
constexpr int OFF_W2 = OFF_W1 + 2 * W1_BUF;          // 115200
constexpr int OFF_B1 = OFF_W2 + 2 * W2_BUF;          // 121344
constexpr int OFF_B2 = OFF_B1 + T_ * H_ * 4;         // 129536
constexpr int SMEM_TOTAL = OFF_B2 + E_ * 4;          // 129792
// W3 bf16 [n][e] staging overlays the dead BE ring in the epilogue
constexpr int OFF_W3S = 0;                  // 256 rows x 144B

// ---------------------------------------------------------------------------
// Kernel 2: fully fused stages 2..7. CTA = tree i, 512 threads = 16 warps,
// warp w owns batch rows [16w,16w+16). All fragment loads via ldmatrix.x4.
// ---------------------------------------------------------------------------
__global__ void __launch_bounds__(512, 1)
fused_all_kernel(const float* __restrict__ lin1,   // [T,T,E,H]
                 const float* __restrict__ b1,     // [T,T,H]
                 const float* __restrict__ lin2,   // [T,(T-1)*H,E]
                 const float* __restrict__ b2,     // [T,E]
                 const float* __restrict__ w3g,    // [T,E,N]
                 const int*   __restrict__ x,      // [B,T]
                 float* __restrict__ out) {        // [B,T]
    extern __shared__ char smem[];
    const int i    = blockIdx.x;
    const int tid  = threadIdx.x;
    const int w    = tid >> 5;
    const int lane = tid & 31;
    const int q    = lane & 3;
    const int r4   = lane >> 2;

    float* sb1 = reinterpret_cast<float*>(smem + OFF_B1);
    float* sb2 = reinterpret_cast<float*>(smem + OFF_B2);
    const uint32_t smem_u32 = (uint32_t)__cvta_generic_to_shared(smem);

    // ldmatrix lane-dependent base offsets (hoisted):
    // A tiles (BE / m16k16): row = w*16 + (lane&15), colByte = (lane>>4)*16
    const uint32_t a_off = smem_u32 + OFF_BE +
        (w * 16 + (lane & 15)) * BE_STRIDE + (lane >> 4) * 16;
    // B tiles (n-rows, k-cols): row = (lane&7) + ((lane>>1)&8),
    //                           colByte = ((lane>>3)&1)*16
    const int brow = (lane & 7) + ((lane >> 1) & 8);
    const int bcol = ((lane >> 3) & 1) * 16;
    const uint32_t w1_off = smem_u32 + OFF_W1 + brow * W1_STRIDE + bcol;
    const uint32_t w2_off = smem_u32 + OFF_W2 + brow * W2_STRIDE + bcol;
    const uint32_t w3_off = smem_u32 + OFF_W3S + brow * 144 + bcol;

    auto jof = [&](int jj) { return jj + (jj >= i); };

    auto stage_be = [&](int buf, int j) {
        uint32_t dst0 = smem_u32 + OFF_BE + buf * BE_BUF;
        const char* src =
            reinterpret_cast<const char*>(g_be + (size_t)j * B_ * E_);
#pragma unroll
        for (int u = 0; u < 4; ++u) {
            int c = tid + 512 * u;             // 2048 x 16B chunks
            int row = c >> 3, off = c & 7;
            CP_ASYNC16(dst0 + row * BE_STRIDE + off * 16, src + c * 16);
        }
    };

    struct WRegs { float2 v1, v2; };
    auto ldg_w = [&](int j) {
        WRegs r;
        r.v1 = reinterpret_cast<const float2*>(
            lin1 + (size_t)(i * T_ + j) * (E_ * H_))[tid];
        int kk = (j < i) ? j : j - 1;
        r.v2 = reinterpret_cast<const float2*>(
            lin2 + ((size_t)i * K2_ + (size_t)kk * H_) * E_)[tid];
        return r;
    };
    auto sts_w = [&](int buf, const WRegs& r) {
        __nv_bfloat16* w1 =
            reinterpret_cast<__nv_bfloat16*>(smem + OFF_W1 + buf * W1_BUF);
        {
            int idx = tid * 2;
            const float* f = reinterpret_cast<const float*>(&r.v1);
#pragma unroll
            for (int s = 0; s < 2; ++s) {
                int e = (idx + s) >> 4, hh = (idx + s) & 15;
                w1[hh * (W1_STRIDE / 2) + e] = __float2bfloat16(f[s]);
            }
        }
        __nv_bfloat16* w2 =
            reinterpret_cast<__nv_bfloat16*>(smem + OFF_W2 + buf * W2_BUF);
        {
            int idx = tid * 2;
            const float* f = reinterpret_cast<const float*>(&r.v2);
#pragma unroll
            for (int s = 0; s < 2; ++s) {
                int k = (idx + s) >> 6, e = (idx + s) & 63;
                w2[e * (W2_STRIDE / 2) + k] = __float2bfloat16(f[s]);
            }
        }
    };

    // ---- prologue ----------------------------------------------------------
#pragma unroll
    for (int u = 0; u < 4; ++u)
        sb1[tid + 512 * u] = b1[(size_t)i * T_ * H_ + tid + 512 * u];
    if (tid < E_) sb2[tid] = b2[(size_t)i * E_ + tid];

    stage_be(0, jof(0)); CP_COMMIT();
    WRegs w0 = ldg_w(jof(0));
    sts_w(0, w0);
    stage_be(1, jof(1)); CP_COMMIT();
    WRegs wr = ldg_w(jof(1));              // invariant: wr = W(jj+1)

    float zacc[8][4];
#pragma unroll
    for (int nt = 0; nt < 8; ++nt)
#pragma unroll
        for (int s = 0; s < 4; ++s) zacc[nt][s] = 0.f;

    // ---- main loop over jj (j != i) ---------------------------------------
    for (int jj = 0; jj < T_ - 1; ++jj) {
        const int j = jof(jj);

        CP_WAIT1();              // BE(jj) complete
        __syncthreads();

        if (jj + 1 < T_ - 1) sts_w((jj + 1) & 1, wr);
        if (jj + 2 < T_ - 1) {
            wr = ldg_w(jof(jj + 2));
            stage_be((jj + 2) % 3, jof(jj + 2));
        }
        CP_COMMIT();             // one group per iteration (maybe empty)

        const uint32_t beb = a_off  + (jj % 3) * BE_BUF;
        const uint32_t w1b = w1_off + (jj & 1) * W1_BUF;
        const uint32_t w2b = w2_off + (jj & 1) * W2_BUF;

        // A-fragments: 4x ldmatrix.x4 (m16k64 strip)
        uint32_t a[4][4];
#pragma unroll
        for (int kt = 0; kt < 4; ++kt)
            LDSM_X4(a[kt][0], a[kt][1], a[kt][2], a[kt][3], beb + kt * 32);

        // GEMM1: tmp[16,16] = BE[16,64] @ W1[64,16] (+bias1)
        float c1[2][4];
#pragma unroll
        for (int nt = 0; nt < 2; ++nt) {
            float bv0 = sb1[j * H_ + nt * 8 + 2 * q];
            float bv1 = sb1[j * H_ + nt * 8 + 2 * q + 1];
            c1[nt][0] = bv0; c1[nt][1] = bv1;
            c1[nt][2] = bv0; c1[nt][3] = bv1;
        }
#pragma unroll
        for (int kt = 0; kt < 4; ++kt) {
            uint32_t b0, b1r, b2r, b3;
            LDSM_X4(b0, b1r, b2r, b3, w1b + kt * 32);
            mma_bf16(c1[0], a[kt], b0, b1r);
            mma_bf16(c1[1], a[kt], b2r, b3);
        }

        // relu + cvt C-frags -> GEMM2 A-frag (registers only)
#pragma unroll
        for (int nt = 0; nt < 2; ++nt)
#pragma unroll
            for (int s = 0; s < 4; ++s) c1[nt][s] = fmaxf(c1[nt][s], 0.f);
        uint32_t a2[4];
        {
            __nv_bfloat162 p0 = __floats2bfloat162_rn(c1[0][0], c1[0][1]);
            __nv_bfloat162 p1 = __floats2bfloat162_rn(c1[0][2], c1[0][3]);
            __nv_bfloat162 p2 = __floats2bfloat162_rn(c1[1][0], c1[1][1]);
            __nv_bfloat162 p3 = __floats2bfloat162_rn(c1[1][2], c1[1][3]);
            a2[0] = *reinterpret_cast<uint32_t*>(&p0);
            a2[1] = *reinterpret_cast<uint32_t*>(&p1);
            a2[2] = *reinterpret_cast<uint32_t*>(&p2);
            a2[3] = *reinterpret_cast<uint32_t*>(&p3);
        }

        // GEMM2: z[16,64] += tmp[16,16] @ W2[16,64]
#pragma unroll
        for (int p = 0; p < 4; ++p) {
            uint32_t b0, b1r, b2r, b3;
            LDSM_X4(b0, b1r, b2r, b3, w2b + p * 16 * W2_STRIDE);
            mma_bf16(zacc[2 * p + 0], a2, b0, b1r);
            mma_bf16(zacc[2 * p + 1], a2, b2r, b3);
        }
    }

    // ======================= fused CE head ==================================
    CP_WAIT0();
    __syncthreads();             // BE ring dead; reuse as W3 staging

    // W3[i] fp32 [e][n] -> smem bf16 [n][e] (rows 144B)
    {
        const float4* w3p =
            reinterpret_cast<const float4*>(w3g + (size_t)i * E_ * N_);
        __nv_bfloat16* W3S = reinterpret_cast<__nv_bfloat16*>(smem + OFF_W3S);
#pragma unroll
        for (int it = 0; it < 8; ++it) {
            int idx = it * 512 + tid;          // 4096 float4 total
            float4 f = w3p[idx];
            int e = idx >> 6, n0 = (idx & 63) * 4;
            W3S[(n0 + 0) * 72 + e] = __float2bfloat16(f.x);
            W3S[(n0 + 1) * 72 + e] = __float2bfloat16(f.y);
            W3S[(n0 + 2) * 72 + e] = __float2bfloat16(f.z);
            W3S[(n0 + 3) * 72 + e] = __float2bfloat16(f.w);
        }
    }

    // z + bias2 -> bf16 A-fragments
    uint32_t az[4][4];
#pragma unroll
    for (int kt = 0; kt < 4; ++kt) {
        float v[2][4];
#pragma unroll
        for (int p = 0; p < 2; ++p) {
            int nt = 2 * kt + p;
            float bx = sb2[nt * 8 + 2 * q], by = sb2[nt * 8 + 2 * q + 1];
            v[p][0] = zacc[nt][0] + bx; v[p][1] = zacc[nt][1] + by;
            v[p][2] = zacc[nt][2] + bx; v[p][3] = zacc[nt][3] + by;
        }
        __nv_bfloat162 p0 = __floats2bfloat162_rn(v[0][0], v[0][1]);
        __nv_bfloat162 p1 = __floats2bfloat162_rn(v[0][2], v[0][3]);
        __nv_bfloat162 p2 = __floats2bfloat162_rn(v[1][0], v[1][1]);
        __nv_bfloat162 p3 = __floats2bfloat162_rn(v[1][2], v[1][3]);
        az[kt][0] = *reinterpret_cast<uint32_t*>(&p0);
        az[kt][1] = *reinterpret_cast<uint32_t*>(&p1);
        az[kt][2] = *reinterpret_cast<uint32_t*>(&p2);
        az[kt][3] = *reinterpret_cast<uint32_t*>(&p3);
    }

    int xv[2];
    xv[0] = x[(size_t)(w * 16 + r4) * T_ + i];
    xv[1] = x[(size_t)(w * 16 + r4 + 8) * T_ + i];

    __syncthreads();             // W3S ready

    float sum[2] = {0.f, 0.f};
    float picked[2] = {0.f, 0.f};

#pragma unroll
    for (int n0 = 0; n0 < 4; ++n0) {           // 64 classes per chunk
        float c[8][4];
#pragma unroll
        for (int nt = 0; nt < 8; ++nt)
#pragma unroll
            for (int s = 0; s < 4; ++s) c[nt][s] = 0.f;
#pragma unroll
        for (int ntp = 0; ntp < 4; ++ntp) {
#pragma unroll
            for (int kt = 0; kt < 4; ++kt) {
                uint32_t b0, b1r, b2r, b3;
                LDSM_X4(b0, b1r, b2r, b3,
                        w3_off + (n0 * 64 + ntp * 16) * 144 + kt * 32);
                mma_bf16(c[2 * ntp + 0], az[kt], b0, b1r);
                mma_bf16(c[2 * ntp + 1], az[kt], b2r, b3);
            }
        }
#pragma unroll
        for (int nt = 0; nt < 8; ++nt)
#pragma unroll
            for (int s = 0; s < 4; ++s) {
                int n = n0 * 64 + nt * 8 + 2 * q + (s & 1);
                int hh = s >> 1;
                float v = c[nt][s];
                sum[hh] += __expf(v);
                if (n == xv[hh]) picked[hh] = v;
            }
    }

    // reduce over the 4 q-lanes (consecutive lanes r4*4+q)
#pragma unroll
    for (int hh = 0; hh < 2; ++hh) {
        float s = sum[hh], p = picked[hh];
        s += __shfl_xor_sync(0xffffffffu, s, 1);
        s += __shfl_xor_sync(0xffffffffu, s, 2);
        p += __shfl_xor_sync(0xffffffffu, p, 1);
        p += __shfl_xor_sync(0xffffffffu, p, 2);
        if (q == 0) {
            int row = w * 16 + r4 + 8 * hh;
            out[(size_t)row * T_ + i] = __logf(s) - p;
        }
    }
}

// ---------------------------------------------------------------------------
extern "C" void kernel_launch(void* const* d_in, const int* in_sizes, int n_in,
                              void* d_out, int out_size) {
    const int*   x    = (const int*)  d_in[0];  // [B,T]
    const float* emb  = (const float*)d_in[1];  // [N*T,E]
    const float* lin1 = (const float*)d_in[2];  // [T,T,E,H]
    const float* b1   = (const float*)d_in[3];  // [T,T,H]
    const float* lin2 = (const float*)d_in[4];  // [T,(T-1)*H,E]
    const float* b2   = (const float*)d_in[5];  // [T,E]
    const float* w3   = (const float*)d_in[6];  // [T,E,N]
    float* out = (float*)d_out;                 // [B,T]

    cudaFuncSetAttribute(fused_all_kernel,
                         cudaFuncAttributeMaxDynamicSharedMemorySize,
                         SMEM_TOTAL);

    gather_bf16_kernel<<<dim3(T_, B_ / 64), 128>>>(x, emb);
    fused_all_kernel<<<T_, 512, SMEM_TOTAL>>>(lin1, b1, lin2, b2, w3, x, out);
}